// round 1
// baseline (speedup 1.0000x reference)
#include <cuda_runtime.h>

// ESSAttn: b=8, C=64, H=W=256, N=65536
// Layouts: x, scratch (q2n,k2d,v), out are all [b][C][N]  (b<<22 | c<<16 | n)

#define NPIX 65536
#define CHN  64
#define NBAT 8

// scratch (device globals: allocation-free per harness rules)
__device__ float g_q2n[(size_t)NBAT * CHN * NPIX];
__device__ float g_k2d[(size_t)NBAT * CHN * NPIX];
__device__ float g_v  [(size_t)NBAT * CHN * NPIX];
__device__ float g_M  [NBAT * CHN * CHN];
__device__ float g_css[NBAT * CHN];
__device__ float g_kv [NBAT * CHN * CHN];

// ---------------------------------------------------------------------------
__global__ void essa_zero() {
    int i = blockIdx.x * 256 + threadIdx.x;
    if (i < NBAT * CHN * CHN) g_M[i] = 0.f;
    if (i < NBAT * CHN)       g_css[i] = 0.f;
}

// ---------------------------------------------------------------------------
// 64x64 row GEMM: row[j] = sum_c xr[c]*W[j][c] + B[j], ILP-4 partial sums,
// weights broadcast from smem as float4 (4 FMA per LDS.128).
__device__ __forceinline__ void gemm64(const float* __restrict__ xr,
                                       const float* __restrict__ sW,
                                       const float* __restrict__ sB,
                                       float* __restrict__ row) {
#pragma unroll 2
    for (int j = 0; j < 64; ++j) {
        const float4* wr = reinterpret_cast<const float4*>(sW + (j << 6));
        float s0 = 0.f, s1 = 0.f, s2 = 0.f, s3 = 0.f;
#pragma unroll
        for (int c4 = 0; c4 < 16; ++c4) {
            float4 w4 = wr[c4];
            s0 = fmaf(xr[4 * c4 + 0], w4.x, s0);
            s1 = fmaf(xr[4 * c4 + 1], w4.y, s1);
            s2 = fmaf(xr[4 * c4 + 2], w4.z, s2);
            s3 = fmaf(xr[4 * c4 + 3], w4.w, s3);
        }
        row[j] = (s0 + s1) + (s2 + s3) + sB[j];
    }
}

// ---------------------------------------------------------------------------
// Kernel A: fused qkv projection + per-row stats. One thread per pixel n.
__global__ __launch_bounds__(256) void essa_qkv(const float* __restrict__ x,
                                                const float* __restrict__ wqkv,
                                                const float* __restrict__ bqkv) {
    const int n = (blockIdx.x << 8) + threadIdx.x;
    const int b = blockIdx.y;
    const size_t base = (size_t)b << 22;

    __shared__ float sW[4096];
    __shared__ float sB[64];

    float xr[64];
#pragma unroll
    for (int c = 0; c < 64; ++c) xr[c] = x[base + ((size_t)c << 16) + n];

    float row[64];  // local-memory staging for stats passes

    // ---------------- Q ----------------
    for (int i = threadIdx.x; i < 4096; i += 256) sW[i] = wqkv[i];
    if (threadIdx.x < 64) sB[threadIdx.x] = bqkv[threadIdx.x];
    __syncthreads();
    gemm64(xr, sW, sB, row);
    {
        float mean = 0.f;
#pragma unroll 8
        for (int j = 0; j < 64; ++j) mean += row[j];
        mean *= (1.f / 64.f);
        float ss = 0.f;
#pragma unroll 8
        for (int j = 0; j < 64; ++j) { float t = row[j] - mean; t = t * t; row[j] = t; ss += t; }
        float inv = 1.f / (ss + 1e-7f);
        float nr = 0.f;
#pragma unroll 8
        for (int j = 0; j < 64; ++j) { float t = row[j] * inv; nr = fmaf(t, t, nr); }
        float sc = inv / fmaxf(sqrtf(nr), 1e-12f);
#pragma unroll 8
        for (int j = 0; j < 64; ++j) g_q2n[base + ((size_t)j << 16) + n] = row[j] * sc;
    }

    // ---------------- K ----------------
    __syncthreads();
    for (int i = threadIdx.x; i < 4096; i += 256) sW[i] = wqkv[4096 + i];
    if (threadIdx.x < 64) sB[threadIdx.x] = bqkv[64 + threadIdx.x];
    __syncthreads();
    gemm64(xr, sW, sB, row);
    {
        float mean = 0.f;
#pragma unroll 8
        for (int j = 0; j < 64; ++j) mean += row[j];
        mean *= (1.f / 64.f);
        float ss = 0.f;
#pragma unroll 8
        for (int j = 0; j < 64; ++j) { float t = row[j] - mean; t = t * t; row[j] = t; ss += t; }
        float inv = 1.f / (ss + 1e-7f);
#pragma unroll 8
        for (int j = 0; j < 64; ++j) g_k2d[base + ((size_t)j << 16) + n] = row[j] * inv;
    }

    // ---------------- V ----------------
    __syncthreads();
    for (int i = threadIdx.x; i < 4096; i += 256) sW[i] = wqkv[8192 + i];
    if (threadIdx.x < 64) sB[threadIdx.x] = bqkv[128 + threadIdx.x];
    __syncthreads();
    gemm64(xr, sW, sB, row);
#pragma unroll 8
    for (int j = 0; j < 64; ++j) g_v[base + ((size_t)j << 16) + n] = row[j];
}

// ---------------------------------------------------------------------------
// Kernel M: M[c][d] += sum_n k2d[n][c]*v[n][d]  (64x64, K-chunked over n),
// plus column sum-of-squares of k2d. 16x16 threads, 4x4 register tile each.
__global__ __launch_bounds__(256) void essa_kvacc() {
    const int b = blockIdx.y;
    const int n0 = blockIdx.x << 9;  // 512 pixels per block
    const size_t base = (size_t)b << 22;

    __shared__ float ks[64 * 33];
    __shared__ float vs[64 * 33];

    const int ty = threadIdx.x >> 4;
    const int tx = threadIdx.x & 15;

    float acc[4][4];
#pragma unroll
    for (int i = 0; i < 4; ++i)
#pragma unroll
        for (int j = 0; j < 4; ++j) acc[i][j] = 0.f;
    float cssr = 0.f;

    for (int t = 0; t < 16; ++t) {
        const int nb = n0 + (t << 5);
        __syncthreads();
        for (int i = threadIdx.x; i < 2048; i += 256) {
            int c = i >> 5, nn = i & 31;
            size_t g = base + ((size_t)c << 16) + nb + nn;
            ks[c * 33 + nn] = g_k2d[g];
            vs[c * 33 + nn] = g_v[g];
        }
        __syncthreads();
        const float* kp = ks + (ty << 2) * 33;
        const float* vp = vs + (tx << 2) * 33;
#pragma unroll 8
        for (int nn = 0; nn < 32; ++nn) {
            float k0 = kp[nn], k1 = kp[33 + nn], k2 = kp[66 + nn], k3 = kp[99 + nn];
            float v0 = vp[nn], v1 = vp[33 + nn], v2 = vp[66 + nn], v3 = vp[99 + nn];
            acc[0][0] = fmaf(k0, v0, acc[0][0]); acc[0][1] = fmaf(k0, v1, acc[0][1]);
            acc[0][2] = fmaf(k0, v2, acc[0][2]); acc[0][3] = fmaf(k0, v3, acc[0][3]);
            acc[1][0] = fmaf(k1, v0, acc[1][0]); acc[1][1] = fmaf(k1, v1, acc[1][1]);
            acc[1][2] = fmaf(k1, v2, acc[1][2]); acc[1][3] = fmaf(k1, v3, acc[1][3]);
            acc[2][0] = fmaf(k2, v0, acc[2][0]); acc[2][1] = fmaf(k2, v1, acc[2][1]);
            acc[2][2] = fmaf(k2, v2, acc[2][2]); acc[2][3] = fmaf(k2, v3, acc[2][3]);
            acc[3][0] = fmaf(k3, v0, acc[3][0]); acc[3][1] = fmaf(k3, v1, acc[3][1]);
            acc[3][2] = fmaf(k3, v2, acc[3][2]); acc[3][3] = fmaf(k3, v3, acc[3][3]);
        }
        if (threadIdx.x < 64) {
            const float* cp = ks + threadIdx.x * 33;
#pragma unroll 8
            for (int nn = 0; nn < 32; ++nn) { float u = cp[nn]; cssr = fmaf(u, u, cssr); }
        }
    }

    float* Mp = g_M + (b << 12);
#pragma unroll
    for (int i = 0; i < 4; ++i)
#pragma unroll
        for (int j = 0; j < 4; ++j)
            atomicAdd(&Mp[((ty << 2) + i) * 64 + (tx << 2) + j], acc[i][j]);
    if (threadIdx.x < 64) atomicAdd(&g_css[(b << 6) + threadIdx.x], cssr);
}

// ---------------------------------------------------------------------------
// kv[c][d] = M[c][d] / max(||k2d[:,c]||, 1e-12)   (exact: scalar commutes)
__global__ void essa_kvfin() {
    int b = blockIdx.x;
    for (int i = threadIdx.x; i < 4096; i += 256) {
        int c = i >> 6;
        float nrm = fmaxf(sqrtf(g_css[(b << 6) + c]), 1e-12f);
        g_kv[(b << 12) + i] = g_M[(b << 12) + i] / nrm;
    }
}

// ---------------------------------------------------------------------------
// Kernel C: t2 = q2n @ kv / sqrt(N); attn = v + t2; out = attn @ w_ln^T + b_ln
__global__ __launch_bounds__(256) void essa_out(const float* __restrict__ wln,
                                                const float* __restrict__ bln,
                                                float* __restrict__ out) {
    const int n = (blockIdx.x << 8) + threadIdx.x;
    const int b = blockIdx.y;
    const size_t base = (size_t)b << 22;

    __shared__ float sKVt[4096];  // kv transposed: sKVt[d][c] = kv[c][d]
    __shared__ float sWl[4096];
    __shared__ float sBl[64];

    for (int i = threadIdx.x; i < 4096; i += 256) {
        int c = i >> 6, d = i & 63;
        sKVt[(d << 6) + c] = g_kv[(b << 12) + i];
        sWl[i] = wln[i];
    }
    if (threadIdx.x < 64) sBl[threadIdx.x] = bln[threadIdx.x];
    __syncthreads();

    float qr[64];
#pragma unroll
    for (int c = 0; c < 64; ++c) qr[c] = g_q2n[base + ((size_t)c << 16) + n];

    float attn[64];
#pragma unroll 2
    for (int d = 0; d < 64; ++d) {
        const float4* kr = reinterpret_cast<const float4*>(sKVt + (d << 6));
        float s0 = 0.f, s1 = 0.f, s2 = 0.f, s3 = 0.f;
#pragma unroll
        for (int c4 = 0; c4 < 16; ++c4) {
            float4 w4 = kr[c4];
            s0 = fmaf(qr[4 * c4 + 0], w4.x, s0);
            s1 = fmaf(qr[4 * c4 + 1], w4.y, s1);
            s2 = fmaf(qr[4 * c4 + 2], w4.z, s2);
            s3 = fmaf(qr[4 * c4 + 3], w4.w, s3);
        }
        float t2 = ((s0 + s1) + (s2 + s3)) * (1.f / 256.f);  // / sqrt(N)
        attn[d] = g_v[base + ((size_t)d << 16) + n] + t2;
    }

    float ar[64];
#pragma unroll
    for (int d = 0; d < 64; ++d) ar[d] = attn[d];

#pragma unroll 2
    for (int dd = 0; dd < 64; ++dd) {
        const float4* wr = reinterpret_cast<const float4*>(sWl + (dd << 6));
        float s0 = 0.f, s1 = 0.f, s2 = 0.f, s3 = 0.f;
#pragma unroll
        for (int c4 = 0; c4 < 16; ++c4) {
            float4 w4 = wr[c4];
            s0 = fmaf(ar[4 * c4 + 0], w4.x, s0);
            s1 = fmaf(ar[4 * c4 + 1], w4.y, s1);
            s2 = fmaf(ar[4 * c4 + 2], w4.z, s2);
            s3 = fmaf(ar[4 * c4 + 3], w4.w, s3);
        }
        out[base + ((size_t)dd << 16) + n] = (s0 + s1) + (s2 + s3) + sBl[dd];
    }
}

// ---------------------------------------------------------------------------
extern "C" void kernel_launch(void* const* d_in, const int* in_sizes, int n_in,
                              void* d_out, int out_size) {
    const float* x    = (const float*)d_in[0];
    const float* wqkv = (const float*)d_in[1];
    const float* bqkv = (const float*)d_in[2];
    const float* wln  = (const float*)d_in[3];
    const float* bln  = (const float*)d_in[4];
    float* out = (float*)d_out;

    essa_zero<<<128, 256>>>();

    dim3 gridA(NPIX / 256, NBAT);
    essa_qkv<<<gridA, 256>>>(x, wqkv, bqkv);

    dim3 gridM(NPIX / 512, NBAT);
    essa_kvacc<<<gridM, 256>>>();

    essa_kvfin<<<NBAT, 256>>>();

    essa_out<<<gridA, 256>>>(wln, bln, out);
}